// round 1
// baseline (speedup 1.0000x reference)
#include <cuda_runtime.h>
#include <cstdint>

#define CAP        500000
#define FDIM       128
#define BATCH      256
#define KNEG       4096
#define ROWS_PER_B (KNEG + 1)   // 4097

// Scratch state (allocation-free). g_pos is zero-initialized at module load;
// every launch restores it to all-zeros (scatter then cleanup), so replays
// are deterministic. Encoding: 0 = row not updated, else (batch_pos + 1).
__device__ int   g_pos[CAP];
__device__ float g_upd_s[BATCH * FDIM];
__device__ float g_upd_t[BATCH * FDIM];

// One block per (which, batch-row): EMA + L2 normalize into scratch.
// blocks 0..255 -> s side, 256..511 -> t side.
__global__ void cm_update_kernel(const float* __restrict__ f_s,
                                 const float* __restrict__ f_t,
                                 const float* __restrict__ mem1,
                                 const float* __restrict__ mem2,
                                 const int*   __restrict__ s_layer_p,
                                 const int*   __restrict__ t_layer_p,
                                 const int*   __restrict__ idx)
{
    const int i     = blockIdx.x & (BATCH - 1);
    const int which = blockIdx.x >> 8;          // 0 = s, 1 = t
    const int t     = threadIdx.x;              // 0..127

    const float* f    = which ? f_t : f_s;
    const float* mem  = which ? mem2 : mem1;
    const int layer   = which ? *t_layer_p : *s_layer_p;
    const int row     = idx[i];

    const float oldv = mem[(size_t)layer * CAP * FDIM + (size_t)row * FDIM + t];
    const float v    = 0.5f * oldv + 0.5f * f[i * FDIM + t];

    // Block reduction of v*v across 128 threads (4 warps).
    float s = v * v;
    #pragma unroll
    for (int o = 16; o; o >>= 1) s += __shfl_xor_sync(0xffffffffu, s, o);
    __shared__ float ws[4];
    if ((t & 31) == 0) ws[t >> 5] = s;
    __syncthreads();
    const float tot = ws[0] + ws[1] + ws[2] + ws[3];

    const float outv = v / sqrtf(tot);
    (which ? g_upd_t : g_upd_s)[i * FDIM + t] = outv;

    if (t == 0 && which == 0) g_pos[row] = i + 1;  // publish updated-row map
}

// One warp per output row (b, j) of each tensor. Lane loads one float4 ->
// warp moves a contiguous 512B row. Rows hitting an updated index read the
// normalized scratch copy instead of stale memory.
__global__ void cm_gather_kernel(const float* __restrict__ mem1,
                                 const float* __restrict__ mem2,
                                 const int*   __restrict__ s_layer_p,
                                 const int*   __restrict__ t_layer_p,
                                 const int*   __restrict__ idx,
                                 const int*   __restrict__ cidx,
                                 float*       __restrict__ out)
{
    const long long per_tensor = (long long)BATCH * ROWS_PER_B;       // 1,048,832
    const long long total      = 2LL * per_tensor;                    // 2,097,664
    const long long wg = (long long)blockIdx.x * (blockDim.x >> 5) + (threadIdx.x >> 5);
    if (wg >= total) return;

    const int       lane  = threadIdx.x & 31;
    const int       which = (wg >= per_tensor);
    const long long r     = which ? (wg - per_tensor) : wg;
    const int       b     = (int)(r / ROWS_PER_B);
    const int       j     = (int)(r - (long long)b * ROWS_PER_B);

    const int src = (j == 0) ? idx[b] : cidx[b * KNEG + (j - 1)];
    const int p   = g_pos[src];

    const float4* sp;
    if (p > 0) {
        const float* upd = which ? g_upd_t : g_upd_s;
        sp = (const float4*)(upd + (size_t)(p - 1) * FDIM);
    } else {
        const float* mem  = which ? mem2 : mem1;
        const int    layer = which ? *t_layer_p : *s_layer_p;
        sp = (const float4*)(mem + (size_t)layer * CAP * FDIM + (size_t)src * FDIM);
    }

    float4* op = (float4*)(out + ((size_t)which * per_tensor + (size_t)r) * FDIM);
    op[lane] = sp[lane];
}

// Restore g_pos to all-zeros for the next (graph-replayed) launch.
__global__ void cm_cleanup_kernel(const int* __restrict__ idx)
{
    g_pos[idx[threadIdx.x]] = 0;
}

extern "C" void kernel_launch(void* const* d_in, const int* in_sizes, int n_in,
                              void* d_out, int out_size)
{
    const float* f_s      = (const float*)d_in[0];
    const float* f_t      = (const float*)d_in[1];
    const float* mem1     = (const float*)d_in[2];
    const float* mem2     = (const float*)d_in[3];
    const int*   s_layer  = (const int*)  d_in[4];
    const int*   t_layer  = (const int*)  d_in[5];
    const int*   idx      = (const int*)  d_in[6];
    const int*   cidx     = (const int*)  d_in[7];
    float*       out      = (float*)d_out;

    cm_update_kernel<<<2 * BATCH, FDIM>>>(f_s, f_t, mem1, mem2, s_layer, t_layer, idx);

    const long long total_rows = 2LL * BATCH * ROWS_PER_B;  // 2,097,664
    const int warps_per_block  = 8;                          // 256 threads
    const int nblocks = (int)((total_rows + warps_per_block - 1) / warps_per_block);
    cm_gather_kernel<<<nblocks, warps_per_block * 32>>>(mem1, mem2, s_layer, t_layer,
                                                        idx, cidx, out);

    cm_cleanup_kernel<<<1, BATCH>>>(idx);
}

// round 2
// speedup vs baseline: 1.0290x; 1.0290x over previous
#include <cuda_runtime.h>
#include <cstdint>

#define CAP        500000
#define FDIM       128
#define BATCH      256
#define KNEG       4096
#define ROWS_PER_B (KNEG + 1)   // 4097

// Scratch state (allocation-free). g_pos is zero-initialized at module load;
// every launch restores it to all-zeros (scatter then cleanup), so replays
// are deterministic. Encoding: 0 = row not updated, else (batch_pos + 1).
__device__ int   g_pos[CAP];
__device__ float g_upd_s[BATCH * FDIM];
__device__ float g_upd_t[BATCH * FDIM];

// One block per (which, batch-row): EMA + L2 normalize into scratch.
__global__ void cm_update_kernel(const float* __restrict__ f_s,
                                 const float* __restrict__ f_t,
                                 const float* __restrict__ mem1,
                                 const float* __restrict__ mem2,
                                 const int*   __restrict__ s_layer_p,
                                 const int*   __restrict__ t_layer_p,
                                 const int*   __restrict__ idx)
{
    const int i     = blockIdx.x & (BATCH - 1);
    const int which = blockIdx.x >> 8;          // 0 = s, 1 = t
    const int t     = threadIdx.x;              // 0..127

    const float* f    = which ? f_t : f_s;
    const float* mem  = which ? mem2 : mem1;
    const int layer   = which ? *t_layer_p : *s_layer_p;
    const int row     = idx[i];

    const float oldv = mem[(size_t)layer * CAP * FDIM + (size_t)row * FDIM + t];
    const float v    = 0.5f * oldv + 0.5f * f[i * FDIM + t];

    float s = v * v;
    #pragma unroll
    for (int o = 16; o; o >>= 1) s += __shfl_xor_sync(0xffffffffu, s, o);
    __shared__ float ws[4];
    if ((t & 31) == 0) ws[t >> 5] = s;
    __syncthreads();
    const float tot = ws[0] + ws[1] + ws[2] + ws[3];

    const float outv = v / sqrtf(tot);
    (which ? g_upd_t : g_upd_s)[i * FDIM + t] = outv;

    if (t == 0 && which == 0) g_pos[row] = i + 1;  // publish updated-row map
}

// L2 evict-last load of a float4 (keeps gather rows resident in L2).
__device__ __forceinline__ float4 ld_evict_last(const float4* p, uint64_t pol)
{
    float4 v;
    asm volatile("ld.global.L2::cache_hint.v4.f32 {%0,%1,%2,%3}, [%4], %5;"
                 : "=f"(v.x), "=f"(v.y), "=f"(v.z), "=f"(v.w)
                 : "l"(p), "l"(pol));
    return v;
}

// One warp per output row (which, b, j). Lane loads one float4 -> warp moves
// a contiguous 512B row. Output uses streaming (evict-first) stores so the
// 1.07GB write stream doesn't displace gather rows from L2.
__global__ void cm_gather_kernel(const float* __restrict__ mem1,
                                 const float* __restrict__ mem2,
                                 const int*   __restrict__ s_layer_p,
                                 const int*   __restrict__ t_layer_p,
                                 const int*   __restrict__ idx,
                                 const int*   __restrict__ cidx,
                                 float*       __restrict__ out)
{
    const long long per_tensor = (long long)BATCH * ROWS_PER_B;       // 1,048,832
    const long long total      = 2LL * per_tensor;                    // 2,097,664
    const long long wg = (long long)blockIdx.x * (blockDim.x >> 5) + (threadIdx.x >> 5);
    if (wg >= total) return;

    uint64_t pol;
    asm("createpolicy.fractional.L2::evict_last.b64 %0, 0.8;" : "=l"(pol));

    const int       lane  = threadIdx.x & 31;
    const int       which = (wg >= per_tensor);
    const long long r     = which ? (wg - per_tensor) : wg;
    const int       b     = (int)(r / ROWS_PER_B);
    const int       j     = (int)(r - (long long)b * ROWS_PER_B);

    const int src = (j == 0) ? idx[b] : cidx[b * KNEG + (j - 1)];
    const int p   = g_pos[src];

    float4 v;
    if (p > 0) {
        const float* upd = which ? g_upd_t : g_upd_s;
        v = ((const float4*)(upd + (size_t)(p - 1) * FDIM))[lane];
    } else {
        const float* mem   = which ? mem2 : mem1;
        const int    layer = which ? *t_layer_p : *s_layer_p;
        v = ld_evict_last((const float4*)(mem + (size_t)layer * CAP * FDIM
                                              + (size_t)src * FDIM) + lane, pol);
    }

    float4* op = (float4*)(out + ((size_t)which * per_tensor + (size_t)r) * FDIM);
    __stcs(op + lane, v);
}

// Restore g_pos to all-zeros for the next (graph-replayed) launch.
__global__ void cm_cleanup_kernel(const int* __restrict__ idx)
{
    g_pos[idx[threadIdx.x]] = 0;
}

extern "C" void kernel_launch(void* const* d_in, const int* in_sizes, int n_in,
                              void* d_out, int out_size)
{
    const float* f_s      = (const float*)d_in[0];
    const float* f_t      = (const float*)d_in[1];
    const float* mem1     = (const float*)d_in[2];
    const float* mem2     = (const float*)d_in[3];
    const int*   s_layer  = (const int*)  d_in[4];
    const int*   t_layer  = (const int*)  d_in[5];
    const int*   idx      = (const int*)  d_in[6];
    const int*   cidx     = (const int*)  d_in[7];
    float*       out      = (float*)d_out;

    cm_update_kernel<<<2 * BATCH, FDIM>>>(f_s, f_t, mem1, mem2, s_layer, t_layer, idx);

    const long long total_rows = 2LL * BATCH * ROWS_PER_B;  // 2,097,664
    const int warps_per_block  = 8;                          // 256 threads
    const int nblocks = (int)((total_rows + warps_per_block - 1) / warps_per_block);
    cm_gather_kernel<<<nblocks, warps_per_block * 32>>>(mem1, mem2, s_layer, t_layer,
                                                        idx, cidx, out);

    cm_cleanup_kernel<<<1, BATCH>>>(idx);
}